// round 1
// baseline (speedup 1.0000x reference)
#include <cuda_runtime.h>
#include <math.h>

#define NS 512
#define DD 400
#define HH 400

// ---- scratch (no allocations allowed) ----
__device__ float g_hx[NS * HH];      // x @ W1x^T
__device__ float g_hy[NS * HH];      // y @ W1y^T + b1
__device__ float g_s[NS * NS];       // pre-softplus pair scores (no b2)
__device__ float g_rowLse[NS];
__device__ float g_rowSum[NS];
__device__ float g_diag[NS];

// ======================================================================
// Kernel 1: dual GEMM.  z=0: g_hx = x @ W1[:, :400]^T
//                       z=1: g_hy = y @ W1[:, 400:]^T + b1
// BM=64, BN=64, BK=16, 256 threads, 4x4 register tiles.
// ======================================================================
#define GBM 64
#define GBN 64
#define GBK 16

__global__ void gemm_h_kernel(const float* __restrict__ x,
                              const float* __restrict__ y,
                              const float* __restrict__ W1,
                              const float* __restrict__ b1) {
    const int z = blockIdx.z;
    const float* A = z ? y : x;
    const int woff = z ? DD : 0;
    float* out = z ? g_hy : g_hx;

    const int n0 = blockIdx.x * GBN;   // h dimension (cols, up to 400)
    const int m0 = blockIdx.y * GBM;   // sample dimension (rows, 512)

    __shared__ float As[GBK][GBM + 1];
    __shared__ float Bs[GBK][GBN + 1];

    const int tid = threadIdx.x;       // 256
    const int tx = tid & 15;
    const int ty = tid >> 4;

    float acc[4][4] = {};

    for (int k0 = 0; k0 < DD; k0 += GBK) {
        // Load A tile (64 rows x 16 k), float4, store transposed.
        {
            int m  = tid >> 2;          // 0..63
            int kq = (tid & 3) * 4;     // 0,4,8,12
            float4 v = *reinterpret_cast<const float4*>(&A[(m0 + m) * DD + k0 + kq]);
            As[kq + 0][m] = v.x; As[kq + 1][m] = v.y;
            As[kq + 2][m] = v.z; As[kq + 3][m] = v.w;
        }
        // Load W1 tile (64 h-rows x 16 k), guard h < 400.
        {
            int n  = tid >> 2;
            int kq = (tid & 3) * 4;
            float4 v = make_float4(0.f, 0.f, 0.f, 0.f);
            if (n0 + n < HH)
                v = *reinterpret_cast<const float4*>(&W1[(n0 + n) * (2 * DD) + woff + k0 + kq]);
            Bs[kq + 0][n] = v.x; Bs[kq + 1][n] = v.y;
            Bs[kq + 2][n] = v.z; Bs[kq + 3][n] = v.w;
        }
        __syncthreads();

        #pragma unroll
        for (int kk = 0; kk < GBK; kk++) {
            float a[4], b[4];
            #pragma unroll
            for (int i = 0; i < 4; i++) a[i] = As[kk][ty * 4 + i];
            #pragma unroll
            for (int j = 0; j < 4; j++) b[j] = Bs[kk][tx * 4 + j];
            #pragma unroll
            for (int i = 0; i < 4; i++)
                #pragma unroll
                for (int j = 0; j < 4; j++)
                    acc[i][j] = fmaf(a[i], b[j], acc[i][j]);
        }
        __syncthreads();
    }

    #pragma unroll
    for (int i = 0; i < 4; i++) {
        int m = m0 + ty * 4 + i;
        #pragma unroll
        for (int j = 0; j < 4; j++) {
            int n = n0 + tx * 4 + j;
            if (n < HH) {
                float v = acc[i][j];
                if (z) v += b1[n];
                out[m * HH + n] = v;
            }
        }
    }
}

// ======================================================================
// Kernel 2: pair relu-dot.
//   g_s[i,j] = sum_h relu(g_hy[i,h] + g_hx[j,h]) * W2[h]
// 32x32 output tiles, 256 threads, 2x2 register tiles, BK=16.
// Grid 16x16 = 256 blocks.
// ======================================================================
#define PBK 16

__global__ void pair_kernel(const float* __restrict__ W2) {
    const int j0 = blockIdx.x * 32;   // hx rows (column index of s)
    const int i0 = blockIdx.y * 32;   // hy rows (row index of s)

    __shared__ float Ys[PBK][33];
    __shared__ float Xs[PBK][33];
    __shared__ float Ws[PBK];

    const int tid = threadIdx.x;      // 256
    const int tx = tid & 15;
    const int ty = tid >> 4;

    float acc[2][2] = {};

    for (int k0 = 0; k0 < HH; k0 += PBK) {
        // 32 rows x 16 k per tile = 512 elems; 256 threads -> 2 each.
        #pragma unroll
        for (int it = 0; it < 2; it++) {
            int idx = tid + it * 256;
            int k = idx & (PBK - 1);
            int r = idx >> 4;
            Ys[k][r] = g_hy[(i0 + r) * HH + k0 + k];
            Xs[k][r] = g_hx[(j0 + r) * HH + k0 + k];
        }
        if (tid < PBK) Ws[tid] = W2[k0 + tid];
        __syncthreads();

        #pragma unroll
        for (int kk = 0; kk < PBK; kk++) {
            float w  = Ws[kk];
            float ya = Ys[kk][ty * 2 + 0];
            float yb = Ys[kk][ty * 2 + 1];
            float xa = Xs[kk][tx * 2 + 0];
            float xb = Xs[kk][tx * 2 + 1];
            acc[0][0] = fmaf(fmaxf(ya + xa, 0.f), w, acc[0][0]);
            acc[0][1] = fmaf(fmaxf(ya + xb, 0.f), w, acc[0][1]);
            acc[1][0] = fmaf(fmaxf(yb + xa, 0.f), w, acc[1][0]);
            acc[1][1] = fmaf(fmaxf(yb + xb, 0.f), w, acc[1][1]);
        }
        __syncthreads();
    }

    #pragma unroll
    for (int a = 0; a < 2; a++)
        #pragma unroll
        for (int b = 0; b < 2; b++)
            g_s[(i0 + ty * 2 + a) * NS + (j0 + tx * 2 + b)] = acc[a][b];
}

// ======================================================================
// Kernel 3: per-row reductions over T1 = softplus(s + b2).
// One block (256 threads) per row: logsumexp, sum, diagonal.
// ======================================================================
__device__ __forceinline__ float softplusf(float v) {
    return fmaxf(v, 0.f) + log1pf(expf(-fabsf(v)));
}

__global__ void row_reduce_kernel(const float* __restrict__ b2p) {
    const int i = blockIdx.x;
    const int tid = threadIdx.x;  // 256
    const float b2 = b2p[0];

    float t0 = softplusf(g_s[i * NS + tid] + b2);
    float t1 = softplusf(g_s[i * NS + tid + 256] + b2);

    __shared__ float sm[256];
    __shared__ float diag_sh;
    if (tid == i)       diag_sh = t0;
    if (tid + 256 == i) diag_sh = t1;

    // max
    sm[tid] = fmaxf(t0, t1);
    __syncthreads();
    for (int o = 128; o > 0; o >>= 1) {
        if (tid < o) sm[tid] = fmaxf(sm[tid], sm[tid + o]);
        __syncthreads();
    }
    float m = sm[0];
    __syncthreads();

    // sum of exp(t - m)
    sm[tid] = expf(t0 - m) + expf(t1 - m);
    __syncthreads();
    for (int o = 128; o > 0; o >>= 1) {
        if (tid < o) sm[tid] += sm[tid + o];
        __syncthreads();
    }
    float sumExp = sm[0];
    __syncthreads();

    // sum of T1
    sm[tid] = t0 + t1;
    __syncthreads();
    for (int o = 128; o > 0; o >>= 1) {
        if (tid < o) sm[tid] += sm[tid + o];
        __syncthreads();
    }

    if (tid == 0) {
        g_rowLse[i] = m + logf(sumExp);
        g_rowSum[i] = sm[0];
        g_diag[i]   = diag_sh;
    }
}

// ======================================================================
// Kernel 4: final combine -> out[0] = lower, out[1] = upper
// ======================================================================
__global__ void finalize_kernel(float* __restrict__ out) {
    const int tid = threadIdx.x;  // 512
    __shared__ float sd[512], sl[512], ss[512];
    sd[tid] = g_diag[tid];
    sl[tid] = g_rowLse[tid];
    ss[tid] = g_rowSum[tid];
    __syncthreads();
    for (int o = 256; o > 0; o >>= 1) {
        if (tid < o) {
            sd[tid] += sd[tid + o];
            sl[tid] += sl[tid + o];
            ss[tid] += ss[tid + o];
        }
        __syncthreads();
    }
    if (tid == 0) {
        float n = (float)NS;
        float t0_mean = sd[0] / n;
        float lower = t0_mean - (sl[0] / n - logf(n));
        float upper = t0_mean - ss[0] / (n * n);
        out[0] = lower;
        out[1] = upper;
    }
}

// ======================================================================
extern "C" void kernel_launch(void* const* d_in, const int* in_sizes, int n_in,
                              void* d_out, int out_size) {
    const float* x  = (const float*)d_in[0];
    const float* y  = (const float*)d_in[1];
    const float* W1 = (const float*)d_in[2];
    const float* b1 = (const float*)d_in[3];
    const float* W2 = (const float*)d_in[4];
    const float* b2 = (const float*)d_in[5];
    float* out = (float*)d_out;

    dim3 ggrid((HH + GBN - 1) / GBN, NS / GBM, 2);   // (7, 8, 2)
    gemm_h_kernel<<<ggrid, 256>>>(x, y, W1, b1);

    dim3 pgrid(NS / 32, NS / 32);                    // (16, 16)
    pair_kernel<<<pgrid, 256>>>(W2);

    row_reduce_kernel<<<NS, 256>>>(b2);

    finalize_kernel<<<1, 512>>>(out);
}